// round 3
// baseline (speedup 1.0000x reference)
#include <cuda_runtime.h>

#define N_  4
#define C_  128
#define HW_ 4096
#define W_  64

// Per-(n,k) tap data: base corner index c0, and (fx, fy) with validity folded
// in (invalid -> fx=fy=0 -> all four bilinear coeffs are exactly 0).
__device__ int    g_c0[N_ * HW_];
__device__ float2 g_f [N_ * HW_];

// ---------------------------------------------------------------------------
// Kernel 1: compute taps per (n, k). valid[k] requires in-range in ALL n grids.
// Corners are (c0, c0+1, c0+64, c0+65); coeffs = outer([1-fx, fx], [fx, fy]).
// ---------------------------------------------------------------------------
__global__ void prep_kernel(const float* __restrict__ grid) {
    int k = blockIdx.x * blockDim.x + threadIdx.x;
    if (k >= HW_) return;

    const float2* g2 = (const float2*)grid;  // (N, HW, 2)
    float gx[N_], gy[N_];
    bool valid = true;
#pragma unroll
    for (int n = 0; n < N_; ++n) {
        float2 g = g2[n * HW_ + k];
        gx[n] = g.x;
        gy[n] = g.y;
        valid = valid && (g.x >= -0.001f) && (g.x <= 63.001f)
                      && (g.y >= -0.001f) && (g.y <= 63.001f);
    }

#pragma unroll
    for (int n = 0; n < N_; ++n) {
        float xx = fminf(fmaxf(gx[n], 0.001f), 62.999f);
        float yy = fminf(fmaxf(gy[n], 0.001f), 62.999f);
        float flx = floorf(xx);
        float fly = floorf(yy);
        float fx  = xx - flx;
        float fy  = yy - fly;
        g_c0[n * HW_ + k] = (int)flx * W_ + (int)fly;
        g_f [n * HW_ + k] = valid ? make_float2(fx, fy) : make_float2(0.f, 0.f);
    }
}

// ---------------------------------------------------------------------------
// Kernel 2: one block (512 threads) per (n, c) row. Stage x[n,c,:] as an
// 8B-aligned PAIR array sp[j]=(x[j],x[j+1]) so each corner pair is one
// LDS.64. Staging is built from LDG.128 + 1 scalar, written as STS.128.
// Each thread produces 8 outputs (2 coalesced float4 stores).
// ---------------------------------------------------------------------------
__global__ __launch_bounds__(512, 3)
void gather_kernel(const float* __restrict__ x, float* __restrict__ out) {
    __shared__ float2 sp[HW_];   // 32 KB

    int nc = blockIdx.x;         // 0 .. 511
    int n  = nc >> 7;            // nc / C_

    // Stage: thread handles float4 chunks i and i+512 (i = tid).
    const float*  xr  = x + (size_t)nc * HW_;
    const float4* xr4 = (const float4*)xr;
    float4*       sp4 = (float4*)sp;
#pragma unroll
    for (int i = threadIdx.x; i < HW_ / 4; i += 512) {
        float4 v = xr4[i];
        float  e = (i < HW_ / 4 - 1) ? __ldg(xr + 4 * i + 4) : 0.f;  // sp[4095].y never read
        sp4[2 * i]     = make_float4(v.x, v.y, v.y, v.z);
        sp4[2 * i + 1] = make_float4(v.z, v.w, v.w, e);
    }
    __syncthreads();

    const int4*   c04 = (const int4*)  (g_c0 + n * HW_);
    const float4* f4  = (const float4*)(g_f  + n * HW_);
    float4* o4 = (float4*)(out + (size_t)nc * HW_);

#pragma unroll
    for (int g = 0; g < 2; ++g) {
        int base = g * 512 + threadIdx.x;    // float4 output index (coalesced)
        int4   c  = c04[base];
        float4 fA = f4[2 * base];            // (fx0,fy0, fx1,fy1)
        float4 fB = f4[2 * base + 1];        // (fx2,fy2, fx3,fy3)

        float2 a0 = sp[c.x], b0 = sp[c.x + 64];
        float2 a1 = sp[c.y], b1 = sp[c.y + 64];
        float2 a2 = sp[c.z], b2 = sp[c.z + 64];
        float2 a3 = sp[c.w], b3 = sp[c.w + 64];

        float4 r;
        {
            float u = fA.x * a0.x + fA.y * a0.y;
            float v = fA.x * b0.x + fA.y * b0.y;
            r.x = (1.0f - fA.x) * u + fA.x * v;
        }
        {
            float u = fA.z * a1.x + fA.w * a1.y;
            float v = fA.z * b1.x + fA.w * b1.y;
            r.y = (1.0f - fA.z) * u + fA.z * v;
        }
        {
            float u = fB.x * a2.x + fB.y * a2.y;
            float v = fB.x * b2.x + fB.y * b2.y;
            r.z = (1.0f - fB.x) * u + fB.x * v;
        }
        {
            float u = fB.z * a3.x + fB.w * a3.y;
            float v = fB.z * b3.x + fB.w * b3.y;
            r.w = (1.0f - fB.z) * u + fB.z * v;
        }
        o4[base] = r;
    }
}

extern "C" void kernel_launch(void* const* d_in, const int* in_sizes, int n_in,
                              void* d_out, int out_size) {
    const float* x    = (const float*)d_in[0];   // (4, 128, 4096) f32
    const float* grid = (const float*)d_in[1];   // (4, 64, 64, 2) f32
    float* out = (float*)d_out;                  // (4, 128, 4096) f32

    prep_kernel<<<(HW_ + 255) / 256, 256>>>(grid);
    gather_kernel<<<N_ * C_, 512>>>(x, out);
}